// round 15
// baseline (speedup 1.0000x reference)
#include <cuda_runtime.h>
#include <cuda_fp16.h>
#include <cstdint>

#define Bn  32
#define ICn 512
#define OCn 512

// ---------------- device scratch (no allocation allowed) ----------------
__device__ float g_style[Bn * ICn];
__device__ float g_demod[Bn * OCn];
__device__ float g_wsq[OCn * ICn];
// weights fp16, c1 applied, k sigma-permuted: [72 chunks][512 oc][64 k]
__device__ __align__(16) __half g_mw[72 * 512 * 64];
// modulated input fp16, channel-last, ic sigma-permuted per 16-group
__device__ __align__(16) __half g_xh[(size_t)Bn * 4096 * 512];

// sigma: within a 16-k group, storage position of logical k j, such that the
// m16n8k16 fragment halves (2t,2t+1,2t+8,2t+9) for thread-group t are the
// contiguous 8 bytes at storage offset 8t.
__host__ __device__ __forceinline__ int sigma16(int j) {
    return ((j & 7) >> 1) * 4 + ((j >> 3) & 1) * 2 + (j & 1);
}

// ---------------- prep1: style MLP + weight tiles (4 blocks/oc) ----------------
__global__ void prep1_kernel(const float* __restrict__ w, const float* __restrict__ lin_w,
                             const float* __restrict__ lin_b, const float* __restrict__ conv_w) {
    __shared__ float cw[1152];
    int blk = blockIdx.x, tid = threadIdx.x;       // 256 threads
    if (blk < 32) {
        // style[b,i] = (1/16) * sum_k w[b,k]*lin_w[i,k] + lin_b[i]
        __shared__ float wv[512];
        int b = blk;
        wv[tid] = w[b * 512 + tid];
        wv[tid + 256] = w[b * 512 + tid + 256];
        __syncthreads();
#pragma unroll
        for (int h = 0; h < 2; h++) {
            int i = tid + h * 256;
            float acc = 0.f;
            const float* lr = lin_w + i * 512;
#pragma unroll 8
            for (int k = 0; k < 512; k++) acc += wv[k] * lr[k];
            g_style[b * 512 + i] = acc * (1.0f / 16.0f) + lin_b[i];
        }
    } else {
        // one (oc, ic-quarter) per block: stage 128ic x 9 taps coalesced
        int bi = blk - 32;                 // 2048 blocks
        int oc = bi >> 2, q = bi & 3;      // q selects icb pair {2q, 2q+1}
        const float* src = conv_w + (size_t)oc * 4608 + q * 1152;
        for (int i = tid; i < 1152; i += 256) cw[i] = src[i];
        __syncthreads();
        // wsq for this ic range
        if (tid < 128) {
            int icl = tid;
            float sq = 0.f;
#pragma unroll
            for (int t = 0; t < 9; t++) { float v = cw[icl * 9 + t]; sq += v * v; }
            g_wsq[oc * 512 + q * 128 + icl] = sq;
        }
        // 72 k-groups: one contiguous 32B store each
        if (tid < 72) {
            int g = tid;
            int chunk_l = g >> 2, kg = g & 3;          // chunk_l = icb_l*9 + tap
            int icb_l = chunk_l / 9, tap = chunk_l - icb_l * 9;
            int chunk = (2 * q + icb_l) * 9 + tap;
            __half hbuf[16];
#pragma unroll
            for (int j = 0; j < 16; j++)
                hbuf[sigma16(j)] = __float2half_rn(
                    cw[(icb_l * 64 + kg * 16 + j) * 9 + tap] * (1.0f / 48.0f));  // c1
            uint4* dst = (uint4*)(g_mw + (size_t)chunk * 32768 + oc * 64 + kg * 16);
            dst[0] = ((uint4*)hbuf)[0];
            dst[1] = ((uint4*)hbuf)[1];
        }
    }
}

// ---------------- prep2: demod + modulated channel-last fp16 x ----------------
__global__ void prep2_kernel(const float* __restrict__ x) {
    int tx = threadIdx.x, ty = threadIdx.y;        // 32 x 8
    int t = ty * 32 + tx;
    if (blockIdx.x < 32) {
        __shared__ float s2[512];
        int b = blockIdx.x;
        float sv0 = g_style[b * 512 + t], sv1 = g_style[b * 512 + t + 256];
        s2[t] = sv0 * sv0; s2[t + 256] = sv1 * sv1;
        __syncthreads();
#pragma unroll
        for (int h = 0; h < 2; h++) {
            int o = t + h * 256;
            float acc = 0.f;
            const float* wr = g_wsq + o * 512;
#pragma unroll 8
            for (int i = 0; i < 512; i++) acc += s2[i] * wr[i];
            g_demod[b * 512 + o] = rsqrtf(acc * (1.0f / 2304.0f) + 1e-8f);
        }
    } else {
        __shared__ float tb[32][33];
        int r = blockIdx.x - 32;
        int b = r >> 11;
        int rr = r & 2047;
        int yx0 = (rr >> 4) * 32, ic0 = (rr & 15) * 32;
#pragma unroll
        for (int k = 0; k < 4; k++)
            tb[ty + 8 * k][tx] = x[((size_t)(b * 512 + ic0 + ty + 8 * k) << 12) + yx0 + tx];
        __syncthreads();
#pragma unroll
        for (int k = 0; k < 4; k++) {
            int yx = yx0 + ty + 8 * k;
            int ic = ic0 + tx;
            float v = tb[tx][ty + 8 * k] * g_style[b * 512 + ic];
            int ics = (ic & ~15) | sigma16(ic & 15);
            g_xh[(((size_t)b << 12) + yx) * 512 + ics] = __float2half_rn(v);
        }
    }
}

// ---------------- main conv: halo patch, fp16-acc MMA chains, 4-deep B ring ----------------
#define MMA16816_F16(d0, d1, a, b0_, b1_) \
    asm volatile("mma.sync.aligned.m16n8k16.row.col.f16.f16.f16.f16 " \
        "{%0,%1}, {%2,%3,%4,%5}, {%6,%7}, {%0,%1};" \
        : "+r"(d0), "+r"(d1) \
        : "r"((a)[0]), "r"((a)[1]), "r"((a)[2]), "r"((a)[3]), "r"(b0_), "r"(b1_))

#define CP16(dst, src, sz) \
    asm volatile("cp.async.cg.shared.global [%0], [%1], 16, %2;" \
                 :: "r"(dst), "l"(src), "r"(sz) : "memory")
#define CP_COMMIT() asm volatile("cp.async.commit_group;" ::: "memory")
#define CP_WAIT0()  asm volatile("cp.async.wait_group 0;" ::: "memory")
#define CP_WAIT2()  asm volatile("cp.async.wait_group 2;" ::: "memory")

#define PSTB 144                 // patch/B row stride in bytes (72 fp16)
#define PH_OFF 0                 // 204 * 144 = 29376
#define BB_SZ  18432             // 128 * 144 per buffer
#define B0_OFF 29376
#define SMEM_CONV (29376 + 4 * 18432)   // 103104

__device__ __forceinline__ uint32_t smem_u32(const void* p) {
    uint32_t a;
    asm("{ .reg .u64 t; cvta.to.shared.u64 t, %1; cvt.u32.u64 %0, t; }" : "=r"(a) : "l"(p));
    return a;
}
__device__ __forceinline__ uint2 lds64(const char* p) {
    return *(const uint2*)p;
}

__global__ void __launch_bounds__(256, 2) conv_kernel(
    const float* __restrict__ noise, const float* __restrict__ bias,
    const float* __restrict__ noise_w, float* __restrict__ out)
{
    extern __shared__ __align__(16) char smem[];
    char* const pH = smem + PH_OFF;
    const uint32_t uS = smem_u32(smem);
    const uint32_t uH = uS + PH_OFF;

    const int tid  = threadIdx.x;
    const int lane = tid & 31, wid = tid >> 5;
    const int b   = blockIdx.z;
    const int oc0 = blockIdx.y * 128;
    const int mt  = blockIdx.x;
    const int y0  = (mt >> 1) * 4;                // 4 rows x 32 cols output tile
    const int x0  = (mt & 1) * 32;

    const int wm = wid >> 1, wn = wid & 1;        // warp tile 32m x 64n
    const int gr = lane >> 2, tg = lane & 3;

    float acc[2][8][4];
#pragma unroll
    for (int mi = 0; mi < 2; mi++)
#pragma unroll
        for (int ni = 0; ni < 8; ni++)
#pragma unroll
            for (int r = 0; r < 4; r++) acc[mi][ni][r] = 0.f;

    const int m0base = wm * 32;

    const int bq_oc[4] = { (0 * 256 + tid) >> 3, (1 * 256 + tid) >> 3,
                           (2 * 256 + tid) >> 3, (3 * 256 + tid) >> 3 };
    const int bq_sg = tid & 7;

    for (int icb = 0; icb < 8; icb++) {
        __syncthreads();   // all reads of patch & B ring from prev icb done
        // ---- patch (6 x 34 px, 64 ic) + B taps 0,1 via one cp.async group ----
#pragma unroll
        for (int q = 0; q < 2; q++) {
            int u = tid + q * 256;
            if (u < 408) {
                int pp = u >> 1, hf = u & 1;
                int pr = pp / 34, pc = pp - pr * 34;
                int gy = y0 + pr - 1, gx = x0 + pc - 1;
                bool ok = ((unsigned)gy < 64u) && ((unsigned)gx < 64u);
                uint32_t sz = ok ? 16u : 0u;
                size_t xo = ok ? ((((size_t)b << 12) + gy * 64 + gx) * 512
                                  + icb * 64 + hf * 32) : 0;
                const char* sh = (const char*)(g_xh + xo);
                uint32_t dh = uH + pp * PSTB + hf * 64;
#pragma unroll
                for (int s = 0; s < 4; s++) CP16(dh + s * 16, sh + s * 16, sz);
            }
        }
#pragma unroll
        for (int tp = 0; tp < 2; tp++) {
            const char* src = (const char*)(g_mw + ((size_t)(icb * 9 + tp) * 512 + oc0) * 64);
            uint32_t dB = uS + B0_OFF + tp * BB_SZ;
#pragma unroll
            for (int q = 0; q < 4; q++) {
                int u = q * 256 + tid;
                CP16(dB + bq_oc[q] * PSTB + bq_sg * 16, src + u * 16, 16u);
            }
        }
        CP_COMMIT();
        CP_WAIT0();
        __syncthreads();

        for (int tap = 0; tap < 9; tap++) {
            if (tap && !(tap & 1)) __syncthreads();   // every even tap: ring reuse safe
            if (tap + 2 < 9) {
                const char* src = (const char*)(g_mw + ((size_t)(icb * 9 + tap + 2) * 512 + oc0) * 64);
                uint32_t dB = uS + B0_OFF + ((tap + 2) & 3) * BB_SZ;
#pragma unroll
                for (int q = 0; q < 4; q++) {
                    int u = q * 256 + tid;
                    CP16(dB + bq_oc[q] * PSTB + bq_sg * 16, src + u * 16, 16u);
                }
                CP_COMMIT();
            }
            CP_WAIT2();    // retires exactly the group carrying this tap's B
            const int kh = tap / 3, kw = tap - kh * 3;
            const char* bbase = smem + B0_OFF + (tap & 3) * BB_SZ;

#pragma unroll
            for (int mi = 0; mi < 2; mi++) {
                // load this mi's A fragments for all 4 k-steps
                int ma = m0base + mi * 16 + gr;
                int mb = ma + 8;
                int ia = ((ma >> 5) + kh) * 34 + (ma & 31) + kw;
                int ib = ((mb >> 5) + kh) * 34 + (mb & 31) + kw;
                uint32_t ah[4][4];
#pragma unroll
                for (int ks = 0; ks < 4; ks++) {
                    const int kb = ks * 32 + tg * 8;
                    uint2 aha = lds64(pH + ia * PSTB + kb);
                    uint2 ahb = lds64(pH + ib * PSTB + kb);
                    ah[ks][0] = aha.x; ah[ks][1] = ahb.x;
                    ah[ks][2] = aha.y; ah[ks][3] = ahb.y;
                }
#pragma unroll
                for (int ni = 0; ni < 8; ni++) {
                    int n0 = wn * 64 + ni * 8 + gr;
                    uint2 bf[4];
#pragma unroll
                    for (int ks = 0; ks < 4; ks++)
                        bf[ks] = lds64(bbase + n0 * PSTB + ks * 32 + tg * 8);
                    uint32_t h0 = 0, h1 = 0;          // f16x2 accumulators
#pragma unroll
                    for (int ks = 0; ks < 4; ks++)
                        MMA16816_F16(h0, h1, ah[ks], bf[ks].x, bf[ks].y);
                    // promote tap partial to fp32
                    float2 f0 = __half22float2(*(__half2*)&h0);
                    float2 f1 = __half22float2(*(__half2*)&h1);
                    acc[mi][ni][0] += f0.x;  acc[mi][ni][1] += f0.y;
                    acc[mi][ni][2] += f1.x;  acc[mi][ni][3] += f1.y;
                }
            }
        }
    }

    // ---- epilogue: demod + bias + noise ----
#pragma unroll
    for (int mi = 0; mi < 2; mi++)
#pragma unroll
        for (int ni = 0; ni < 8; ni++) {
            int oc = oc0 + wn * 64 + ni * 8 + tg * 2;
            int m  = m0base + mi * 16 + gr;
            float dm0 = g_demod[b * 512 + oc],  dm1 = g_demod[b * 512 + oc + 1];
            float bs0 = bias[oc],               bs1 = bias[oc + 1];
            float nw0 = noise_w[oc],            nw1 = noise_w[oc + 1];
#pragma unroll
            for (int rr = 0; rr < 2; rr++) {
                int mm = m + rr * 8;
                int yy = y0 + (mm >> 5), xx = x0 + (mm & 31);
                size_t i0 = ((size_t)(b * 512 + oc) << 12) + yy * 64 + xx;
                size_t i1 = i0 + 4096;
                out[i0] = acc[mi][ni][rr * 2 + 0] * dm0 + bs0 + nw0 * noise[i0];
                out[i1] = acc[mi][ni][rr * 2 + 1] * dm1 + bs1 + nw1 * noise[i1];
            }
        }
}

// ---------------------------------------------------------------------------
// Inputs (metadata order): x, w, conv_w, lin_w, lin_b, bias, noise_w, noise
// ---------------------------------------------------------------------------
extern "C" void kernel_launch(void* const* d_in, const int* in_sizes, int n_in,
                              void* d_out, int out_size) {
    (void)in_sizes; (void)n_in; (void)out_size;
    const float* x       = (const float*)d_in[0];
    const float* w       = (const float*)d_in[1];
    const float* conv_w  = (const float*)d_in[2];
    const float* lin_w   = (const float*)d_in[3];
    const float* lin_b   = (const float*)d_in[4];
    const float* bias    = (const float*)d_in[5];
    const float* noise_w = (const float*)d_in[6];
    const float* noise   = (const float*)d_in[7];
    float* out = (float*)d_out;

    cudaFuncSetAttribute(conv_kernel, cudaFuncAttributeMaxDynamicSharedMemorySize, SMEM_CONV);

    // #1: style + weight tiles (4 blocks per oc, coalesced staging)
    prep1_kernel<<<32 + 2048, 256>>>(w, lin_w, lin_b, conv_w);
    // #2: demod + xmod (sigma-permuted channel-last fp16)
    {
        dim3 t(32, 8);
        prep2_kernel<<<32 + Bn * 128 * 16, t>>>(x);
    }
    // #3: conv
    {
        dim3 grid(32, 4, Bn);
        conv_kernel<<<grid, 256, SMEM_CONV>>>(noise, bias, noise_w, out);
    }
}

// round 16
// speedup vs baseline: 1.7683x; 1.7683x over previous
#include <cuda_runtime.h>
#include <cuda_fp16.h>
#include <cstdint>

#define Bn  32
#define ICn 512
#define OCn 512

// ---------------- device scratch (no allocation allowed) ----------------
__device__ float g_style[Bn * ICn];
__device__ float g_demod[Bn * OCn];
__device__ float g_wsqT[ICn * OCn];          // [ic][oc]
__device__ float g_lwT[512 * 512];           // lin_w transposed [k][i]
// weights fp16, c1 applied, ksig2-permuted rows: [72 chunks][512 oc][64 k]
__device__ __align__(16) __half g_mw[72 * 512 * 64];
// modulated input fp16, channel-last, ksig2-permuted per 64-group
__device__ __align__(16) __half g_xh[(size_t)Bn * 4096 * 512];

// ksig2: storage position (halfs) of logical k within a 64-k row:
// pos = tg*16 + ks*4 + intra, tg=(k>>1)&3, ks=(k>>4)&3, intra=((k>>3)&1)*2+(k&1)
__host__ __device__ __forceinline__ int ksig2(int k) {
    return ((k >> 1) & 3) * 16 + ((k >> 4) & 3) * 4 + ((k >> 3) & 1) * 2 + (k & 1);
}

// ---------------- prep0: lin_w transpose + weight tiles + wsqT ----------------
__global__ void prep0_kernel(const float* __restrict__ lin_w, const float* __restrict__ conv_w) {
    __shared__ float sm[1152];
    int blk = blockIdx.x, tid = threadIdx.x;       // 256 threads
    int tx = tid & 31, ty = tid >> 5;              // 32 x 8
    if (blk < 256) {
        // transpose lin_w[i][k] -> g_lwT[k][i], 32x32 tiles
        int i0 = (blk >> 4) * 32, k0 = (blk & 15) * 32;
#pragma unroll
        for (int u = 0; u < 4; u++)
            sm[(ty + 8 * u) * 33 + tx] = lin_w[(size_t)(i0 + ty + 8 * u) * 512 + k0 + tx];
        __syncthreads();
#pragma unroll
        for (int u = 0; u < 4; u++)
            g_lwT[(size_t)(k0 + ty + 8 * u) * 512 + i0 + tx] = sm[tx * 33 + ty + 8 * u];
    } else {
        // one (oc, ic-quarter) per block
        int bi = blk - 256;                // 2048 blocks
        int oc = bi >> 2, q = bi & 3;
        const float* src = conv_w + (size_t)oc * 4608 + q * 1152;
        for (int i = tid; i < 1152; i += 256) sm[i] = src[i];
        __syncthreads();
        if (tid < 128) {
            int icl = tid;
            float sq = 0.f;
#pragma unroll
            for (int t = 0; t < 9; t++) { float v = sm[icl * 9 + t]; sq += v * v; }
            g_wsqT[(size_t)(q * 128 + icl) * 512 + oc] = sq;
        }
        if (tid < 72) {
            int g = tid;
            int chunk_l = g >> 2, kg = g & 3;      // chunk_l = icb_l*9 + tap
            int icb_l = chunk_l / 9, tap = chunk_l - icb_l * 9;
            int chunk = (2 * q + icb_l) * 9 + tap;
#pragma unroll
            for (int t = 0; t < 4; t++) {
                int base = icb_l * 64 + kg * 16 + 2 * t;
                __half h[4];
                h[0] = __float2half_rn(sm[(base)     * 9 + tap] * (1.0f / 48.0f));
                h[1] = __float2half_rn(sm[(base + 1) * 9 + tap] * (1.0f / 48.0f));
                h[2] = __float2half_rn(sm[(base + 8) * 9 + tap] * (1.0f / 48.0f));
                h[3] = __float2half_rn(sm[(base + 9) * 9 + tap] * (1.0f / 48.0f));
                *(uint2*)(g_mw + (size_t)chunk * 32768 + oc * 64 + t * 16 + kg * 4)
                    = *(uint2*)h;
            }
        }
    }
}

// ---------------- prep1: style MLP (coalesced via g_lwT) ----------------
__global__ void prep1_kernel(const float* __restrict__ w, const float* __restrict__ lin_b) {
    __shared__ float wv[512];
    int b = blockIdx.x, tid = threadIdx.x;         // 32 blocks x 256
    wv[tid] = w[b * 512 + tid];
    wv[tid + 256] = w[b * 512 + tid + 256];
    __syncthreads();
#pragma unroll
    for (int h = 0; h < 2; h++) {
        int i = tid + h * 256;
        float acc = 0.f;
#pragma unroll 8
        for (int k = 0; k < 512; k++) acc += wv[k] * g_lwT[(size_t)k * 512 + i];
        g_style[b * 512 + i] = acc * (1.0f / 16.0f) + lin_b[i];   // sqrt(2/512)
    }
}

// ---------------- prep2: demod (coalesced via wsqT) + xmod ----------------
__global__ void prep2_kernel(const float* __restrict__ x) {
    int tx = threadIdx.x, ty = threadIdx.y;        // 32 x 8
    int t = ty * 32 + tx;
    if (blockIdx.x < 32) {
        __shared__ float s2[512];
        int b = blockIdx.x;
        float sv0 = g_style[b * 512 + t], sv1 = g_style[b * 512 + t + 256];
        s2[t] = sv0 * sv0; s2[t + 256] = sv1 * sv1;
        __syncthreads();
#pragma unroll
        for (int h = 0; h < 2; h++) {
            int o = t + h * 256;
            float acc = 0.f;
#pragma unroll 8
            for (int i = 0; i < 512; i++) acc += s2[i] * g_wsqT[(size_t)i * 512 + o];
            g_demod[b * 512 + o] = rsqrtf(acc * (1.0f / 2304.0f) + 1e-8f);
        }
    } else {
        __shared__ float tb[32][33];
        int r = blockIdx.x - 32;
        int b = r >> 11;
        int rr = r & 2047;
        int yx0 = (rr >> 4) * 32, ic0 = (rr & 15) * 32;
#pragma unroll
        for (int k = 0; k < 4; k++)
            tb[ty + 8 * k][tx] = x[((size_t)(b * 512 + ic0 + ty + 8 * k) << 12) + yx0 + tx];
        __syncthreads();
#pragma unroll
        for (int k = 0; k < 4; k++) {
            int yx = yx0 + ty + 8 * k;
            int ic = ic0 + tx;
            float v = tb[tx][ty + 8 * k] * g_style[b * 512 + ic];
            int ics = (ic & ~63) | ksig2(ic & 63);
            g_xh[(((size_t)b << 12) + yx) * 512 + ics] = __float2half_rn(v);
        }
    }
}

// ---------------- main conv: halo patch, fp32-acc HMMA, 4-deep B ring, LDS.128 ----------------
#define MMA16816(d, a, b0_, b1_) \
    asm volatile("mma.sync.aligned.m16n8k16.row.col.f32.f16.f16.f32 " \
        "{%0,%1,%2,%3}, {%4,%5,%6,%7}, {%8,%9}, {%0,%1,%2,%3};" \
        : "+f"((d)[0]), "+f"((d)[1]), "+f"((d)[2]), "+f"((d)[3]) \
        : "r"((a)[0]), "r"((a)[1]), "r"((a)[2]), "r"((a)[3]), "r"(b0_), "r"(b1_))

#define CP16(dst, src, sz) \
    asm volatile("cp.async.cg.shared.global [%0], [%1], 16, %2;" \
                 :: "r"(dst), "l"(src), "r"(sz) : "memory")
#define CP_COMMIT() asm volatile("cp.async.commit_group;" ::: "memory")
#define CP_WAIT0()  asm volatile("cp.async.wait_group 0;" ::: "memory")
#define CP_WAIT2()  asm volatile("cp.async.wait_group 2;" ::: "memory")

#define PSTB 144                 // patch/B row stride in bytes (64 fp16 + pad)
#define PH_OFF 0                 // 204 * 144 = 29376
#define BB_SZ  18432             // 128 * 144 per buffer
#define B0_OFF 29376
#define SMEM_CONV (29376 + 4 * 18432)   // 103104

__device__ __forceinline__ uint32_t smem_u32(const void* p) {
    uint32_t a;
    asm("{ .reg .u64 t; cvta.to.shared.u64 t, %1; cvt.u32.u64 %0, t; }" : "=r"(a) : "l"(p));
    return a;
}
__device__ __forceinline__ uint4 lds128(const char* p) {
    return *(const uint4*)p;
}

__global__ void __launch_bounds__(256, 2) conv_kernel(
    const float* __restrict__ noise, const float* __restrict__ bias,
    const float* __restrict__ noise_w, float* __restrict__ out)
{
    extern __shared__ __align__(16) char smem[];
    char* const pH = smem + PH_OFF;
    const uint32_t uS = smem_u32(smem);
    const uint32_t uH = uS + PH_OFF;

    const int tid  = threadIdx.x;
    const int lane = tid & 31, wid = tid >> 5;
    const int b   = blockIdx.z;
    const int oc0 = blockIdx.y * 128;
    const int mt  = blockIdx.x;
    const int y0  = (mt >> 1) * 4;                // 4 rows x 32 cols output tile
    const int x0  = (mt & 1) * 32;

    const int wm = wid >> 1, wn = wid & 1;        // warp tile 32m x 64n
    const int gr = lane >> 2, tg = lane & 3;

    float acc[2][8][4];
#pragma unroll
    for (int mi = 0; mi < 2; mi++)
#pragma unroll
        for (int ni = 0; ni < 8; ni++)
#pragma unroll
            for (int r = 0; r < 4; r++) acc[mi][ni][r] = 0.f;

    const int m0base = wm * 32;

    const int bq_oc[4] = { (0 * 256 + tid) >> 3, (1 * 256 + tid) >> 3,
                           (2 * 256 + tid) >> 3, (3 * 256 + tid) >> 3 };
    const int bq_sg = tid & 7;

    for (int icb = 0; icb < 8; icb++) {
        __syncthreads();   // all reads of patch & B ring from prev icb done
        // ---- patch (6 x 34 px, 64 ic) + B taps 0,1 via one cp.async group ----
#pragma unroll
        for (int q = 0; q < 2; q++) {
            int u = tid + q * 256;
            if (u < 408) {
                int pp = u >> 1, hf = u & 1;
                int pr = pp / 34, pc = pp - pr * 34;
                int gy = y0 + pr - 1, gx = x0 + pc - 1;
                bool ok = ((unsigned)gy < 64u) && ((unsigned)gx < 64u);
                uint32_t sz = ok ? 16u : 0u;
                size_t xo = ok ? ((((size_t)b << 12) + gy * 64 + gx) * 512
                                  + icb * 64 + hf * 32) : 0;
                const char* sh = (const char*)(g_xh + xo);
                uint32_t dh = uH + pp * PSTB + hf * 64;
#pragma unroll
                for (int s = 0; s < 4; s++) CP16(dh + s * 16, sh + s * 16, sz);
            }
        }
#pragma unroll
        for (int tp = 0; tp < 2; tp++) {
            const char* src = (const char*)(g_mw + ((size_t)(icb * 9 + tp) * 512 + oc0) * 64);
            uint32_t dB = uS + B0_OFF + tp * BB_SZ;
#pragma unroll
            for (int q = 0; q < 4; q++) {
                int u = q * 256 + tid;
                CP16(dB + bq_oc[q] * PSTB + bq_sg * 16, src + u * 16, 16u);
            }
        }
        CP_COMMIT();
        CP_WAIT0();
        __syncthreads();

        for (int tap = 0; tap < 9; tap++) {
            if (tap && !(tap & 1)) __syncthreads();   // every even tap: ring reuse safe
            if (tap + 2 < 9) {
                const char* src = (const char*)(g_mw + ((size_t)(icb * 9 + tap + 2) * 512 + oc0) * 64);
                uint32_t dB = uS + B0_OFF + ((tap + 2) & 3) * BB_SZ;
#pragma unroll
                for (int q = 0; q < 4; q++) {
                    int u = q * 256 + tid;
                    CP16(dB + bq_oc[q] * PSTB + bq_sg * 16, src + u * 16, 16u);
                }
                CP_COMMIT();
            }
            CP_WAIT2();    // retires exactly the group carrying this tap's B
            const int kh = tap / 3, kw = tap - kh * 3;
            const char* bbase = smem + B0_OFF + (tap & 3) * BB_SZ;

#pragma unroll
            for (int pair = 0; pair < 2; pair++) {
                const int off = tg * 32 + pair * 16;   // one LDS.128 = 2 ks-groups
                uint4 bq[8];
#pragma unroll
                for (int ni = 0; ni < 8; ni++) {
                    int n0 = wn * 64 + ni * 8 + gr;
                    bq[ni] = lds128(bbase + n0 * PSTB + off);
                }
#pragma unroll
                for (int mi = 0; mi < 2; mi++) {
                    int ma = m0base + mi * 16 + gr;
                    int mb = ma + 8;
                    int ia = ((ma >> 5) + kh) * 34 + (ma & 31) + kw;
                    int ib = ((mb >> 5) + kh) * 34 + (mb & 31) + kw;
                    uint4 Aa = lds128(pH + ia * PSTB + off);
                    uint4 Ab = lds128(pH + ib * PSTB + off);
                    uint32_t ah0[4] = { Aa.x, Ab.x, Aa.y, Ab.y };   // ks = 2*pair
                    uint32_t ah1[4] = { Aa.z, Ab.z, Aa.w, Ab.w };   // ks = 2*pair+1
#pragma unroll
                    for (int ni = 0; ni < 8; ni++) {
                        MMA16816(acc[mi][ni], ah0, bq[ni].x, bq[ni].y);
                        MMA16816(acc[mi][ni], ah1, bq[ni].z, bq[ni].w);
                    }
                }
            }
        }
    }

    // ---- epilogue: demod + bias + noise ----
#pragma unroll
    for (int mi = 0; mi < 2; mi++)
#pragma unroll
        for (int ni = 0; ni < 8; ni++) {
            int oc = oc0 + wn * 64 + ni * 8 + tg * 2;
            int m  = m0base + mi * 16 + gr;
            float dm0 = g_demod[b * 512 + oc],  dm1 = g_demod[b * 512 + oc + 1];
            float bs0 = bias[oc],               bs1 = bias[oc + 1];
            float nw0 = noise_w[oc],            nw1 = noise_w[oc + 1];
#pragma unroll
            for (int rr = 0; rr < 2; rr++) {
                int mm = m + rr * 8;
                int yy = y0 + (mm >> 5), xx = x0 + (mm & 31);
                size_t i0 = ((size_t)(b * 512 + oc) << 12) + yy * 64 + xx;
                size_t i1 = i0 + 4096;
                out[i0] = acc[mi][ni][rr * 2 + 0] * dm0 + bs0 + nw0 * noise[i0];
                out[i1] = acc[mi][ni][rr * 2 + 1] * dm1 + bs1 + nw1 * noise[i1];
            }
        }
}

// ---------------------------------------------------------------------------
// Inputs (metadata order): x, w, conv_w, lin_w, lin_b, bias, noise_w, noise
// ---------------------------------------------------------------------------
extern "C" void kernel_launch(void* const* d_in, const int* in_sizes, int n_in,
                              void* d_out, int out_size) {
    (void)in_sizes; (void)n_in; (void)out_size;
    const float* x       = (const float*)d_in[0];
    const float* w       = (const float*)d_in[1];
    const float* conv_w  = (const float*)d_in[2];
    const float* lin_w   = (const float*)d_in[3];
    const float* lin_b   = (const float*)d_in[4];
    const float* bias    = (const float*)d_in[5];
    const float* noise_w = (const float*)d_in[6];
    const float* noise   = (const float*)d_in[7];
    float* out = (float*)d_out;

    cudaFuncSetAttribute(conv_kernel, cudaFuncAttributeMaxDynamicSharedMemorySize, SMEM_CONV);

    // #1: lin_w transpose + weight tiles (ksig2) + wsqT
    prep0_kernel<<<256 + 2048, 256>>>(lin_w, conv_w);
    // #2: style MLP (coalesced)
    prep1_kernel<<<32, 256>>>(w, lin_b);
    // #3: demod (coalesced) + xmod (ksig2 channel-last fp16)
    {
        dim3 t(32, 8);
        prep2_kernel<<<32 + Bn * 128 * 16, t>>>(x);
    }
    // #4: conv
    {
        dim3 grid(32, 4, Bn);
        conv_kernel<<<grid, 256, SMEM_CONV>>>(noise, bias, noise_w, out);
    }
}